// round 5
// baseline (speedup 1.0000x reference)
#include <cuda_runtime.h>
#include <cuda_bf16.h>
#include <cstdint>

// Problem constants
#define NN 50000
#define NE 150000
#define DF 512
#define NH 512
#define NC 47
#define NADJ (NE + NN)

// ---------------- scratch (static __device__ — no allocation) ----------------
__device__ int   g_deg[NN];
__device__ __align__(16) float g_dinv[NN];
__device__ int   g_incl[NN];
__device__ int   g_bsum[128];
__device__ int   g_offs[NN + 1];
__device__ int   g_cursor[NN];
__device__ int   g_adj[NADJ];
__device__ __align__(16) float g_h1[(size_t)NN * NH];   // dinv-scaled x@W1
__device__ __align__(16) float g_h2[(size_t)NN * NC];   // dinv-scaled layer2 pre-agg

// ---------------- graph prep ----------------
__global__ void k_init_deg() {
    int i = blockIdx.x * blockDim.x + threadIdx.x;
    if (i < NN) g_deg[i] = 1;  // self loop
}

__global__ void k_count_deg(const int* __restrict__ ecol) {
    int e = blockIdx.x * blockDim.x + threadIdx.x;
    if (e < NE) atomicAdd(&g_deg[ecol[e]], 1);
}

__global__ void k_scan_block() {
    __shared__ int s[512];
    int i = blockIdx.x * 512 + threadIdx.x;
    int v = (i < NN) ? g_deg[i] : 0;
    s[threadIdx.x] = v;
    __syncthreads();
    for (int off = 1; off < 512; off <<= 1) {
        int t = (threadIdx.x >= off) ? s[threadIdx.x - off] : 0;
        __syncthreads();
        s[threadIdx.x] += t;
        __syncthreads();
    }
    if (i < NN) g_incl[i] = s[threadIdx.x];
    if (threadIdx.x == 511) g_bsum[blockIdx.x] = s[511];
}

// parallel exclusive scan of the 98 block sums (one 128-thread block)
__global__ void k_scan_bsum(int nblocks) {
    __shared__ int s[128];
    int t = threadIdx.x;
    int v = (t < nblocks) ? g_bsum[t] : 0;
    s[t] = v;
    __syncthreads();
    for (int off = 1; off < 128; off <<= 1) {
        int u = (t >= off) ? s[t - off] : 0;
        __syncthreads();
        s[t] += u;
        __syncthreads();
    }
    if (t < nblocks) g_bsum[t] = s[t] - v;  // exclusive
}

__global__ void k_scan_finish() {
    int i = blockIdx.x * blockDim.x + threadIdx.x;
    if (i < NN) {
        int e = g_incl[i] - g_deg[i] + g_bsum[i / 512];
        g_offs[i] = e;
        g_cursor[i] = e;
        g_dinv[i] = rsqrtf((float)g_deg[i]);
    }
    if (i == 0) g_offs[NN] = NADJ;
}

__global__ void k_scatter(const int* __restrict__ erow,
                          const int* __restrict__ ecol) {
    int t = blockIdx.x * blockDim.x + threadIdx.x;
    if (t < NE) {
        int c = ecol[t];
        int p = atomicAdd(&g_cursor[c], 1);
        g_adj[p] = erow[t];
    } else if (t < NADJ) {
        int i = t - NE;
        int p = atomicAdd(&g_cursor[i], 1);
        g_adj[p] = i;
    }
}

// ---------------- helpers ----------------
__device__ __forceinline__ uint32_t f2tf32(float f) {
    uint32_t u;
    asm("cvt.rna.tf32.f32 %0, %1;" : "=r"(u) : "f"(f));
    return u;
}

__device__ __forceinline__ void mma_tf32(float& c0, float& c1, float& c2, float& c3,
                                         uint32_t a0, uint32_t a1, uint32_t a2, uint32_t a3,
                                         uint32_t b0, uint32_t b1) {
    asm volatile(
        "mma.sync.aligned.m16n8k8.row.col.f32.tf32.tf32.f32 "
        "{%0,%1,%2,%3},{%4,%5,%6,%7},{%8,%9},{%0,%1,%2,%3};"
        : "+f"(c0), "+f"(c1), "+f"(c2), "+f"(c3)
        : "r"(a0), "r"(a1), "r"(a2), "r"(a3), "r"(b0), "r"(b1));
}

// ---------------- GEMM1 (TF32 tensor cores) ----------------
// g_h1[m,f] = dinv[m] * sum_k x[m,k] * W1[k,f]
// BM=128, BN=128, BK=32; 128 threads = 4 warps (2M x 2N); warp tile 64x64.
__global__ __launch_bounds__(128) void k_gemm1_tf32(const float* __restrict__ A,
                                                    const float* __restrict__ B) {
    __shared__ __align__(16) uint32_t As[128][36];   // [m][k] pad36: a-frag conflict-free
    __shared__ __align__(16) uint32_t Bs[32][136];   // [k][n] pad136: b-frag conflict-free

    const int tid = threadIdx.x;
    const int lane = tid & 31;
    const int warp = tid >> 5;        // 0..3
    const int wm = warp & 1;
    const int wn = warp >> 1;
    const int gp = lane >> 2;         // 0..7
    const int tq = lane & 3;          // 0..3

    const int rowBase = blockIdx.y * 128;
    const int colBase = blockIdx.x * 128;
    const int warpRow = wm * 64;
    const int warpCol = wn * 64;

    float acc[4][8][4];
#pragma unroll
    for (int mi = 0; mi < 4; mi++)
#pragma unroll
        for (int ni = 0; ni < 8; ni++)
#pragma unroll
            for (int j = 0; j < 4; j++) acc[mi][ni][j] = 0.f;

    for (int k0 = 0; k0 < DF; k0 += 32) {
        // ---- A tile: 128 rows x 32 k = 1024 float4 -> 8 per thread
#pragma unroll
        for (int i = 0; i < 8; i++) {
            int fid = tid + i * 128;
            int r = fid >> 3;        // 0..127
            int q = fid & 7;
            int gr = rowBase + r;
            float4 v = make_float4(0.f, 0.f, 0.f, 0.f);
            if (gr < NN) v = __ldg((const float4*)(A + (size_t)gr * DF + k0 + q * 4));
            uint4 u;
            u.x = f2tf32(v.x); u.y = f2tf32(v.y);
            u.z = f2tf32(v.z); u.w = f2tf32(v.w);
            *(uint4*)(&As[r][q * 4]) = u;
        }
        // ---- B tile: 32 k-rows x 128 cols = 1024 float4 -> 8 per thread
#pragma unroll
        for (int i = 0; i < 8; i++) {
            int fid = tid + i * 128;
            int r = fid >> 5;        // 0..31
            int q = fid & 31;
            float4 v = __ldg((const float4*)(B + (size_t)(k0 + r) * NH + colBase + q * 4));
            uint4 u;
            u.x = f2tf32(v.x); u.y = f2tf32(v.y);
            u.z = f2tf32(v.z); u.w = f2tf32(v.w);
            *(uint4*)(&Bs[r][q * 4]) = u;
        }
        __syncthreads();

#pragma unroll
        for (int kk = 0; kk < 32; kk += 8) {
            uint32_t a[4][4];
#pragma unroll
            for (int mi = 0; mi < 4; mi++) {
                int r0 = warpRow + mi * 16 + gp;
                a[mi][0] = As[r0][kk + tq];
                a[mi][1] = As[r0 + 8][kk + tq];
                a[mi][2] = As[r0][kk + tq + 4];
                a[mi][3] = As[r0 + 8][kk + tq + 4];
            }
            uint32_t b[8][2];
#pragma unroll
            for (int ni = 0; ni < 8; ni++) {
                int c = warpCol + ni * 8 + gp;
                b[ni][0] = Bs[kk + tq][c];
                b[ni][1] = Bs[kk + tq + 4][c];
            }
#pragma unroll
            for (int mi = 0; mi < 4; mi++)
#pragma unroll
                for (int ni = 0; ni < 8; ni++)
                    mma_tf32(acc[mi][ni][0], acc[mi][ni][1],
                             acc[mi][ni][2], acc[mi][ni][3],
                             a[mi][0], a[mi][1], a[mi][2], a[mi][3],
                             b[ni][0], b[ni][1]);
        }
        __syncthreads();
    }

    // ---- epilogue: scale rows by dinv, store
#pragma unroll
    for (int mi = 0; mi < 4; mi++) {
        int r0 = rowBase + warpRow + mi * 16 + gp;
        int r1 = r0 + 8;
        float d0 = (r0 < NN) ? g_dinv[r0] : 0.f;
        float d1 = (r1 < NN) ? g_dinv[r1] : 0.f;
#pragma unroll
        for (int ni = 0; ni < 8; ni++) {
            int c = colBase + warpCol + ni * 8 + tq * 2;
            if (r0 < NN) {
                float2 o = make_float2(d0 * acc[mi][ni][0], d0 * acc[mi][ni][1]);
                *(float2*)(g_h1 + (size_t)r0 * NH + c) = o;
            }
            if (r1 < NN) {
                float2 o = make_float2(d1 * acc[mi][ni][2], d1 * acc[mi][ni][3]);
                *(float2*)(g_h1 + (size_t)r1 * NH + c) = o;
            }
        }
    }
}

// ---------------- fused agg1 + GEMM2 (TF32) ----------------
// a1[r,k] = relu(dinv[r] * sum_{p in adj[r]} h1[adj[p],k] + b1[k])   (built on the fly)
// g_h2[m,c] = dinv[m] * sum_k a1[m,k] * W2[k,c]
// BM=128, BN=64 (guarded to 47), BK=32; 256 threads = 8 warps (4M x 2N); warp tile 32x32.
__global__ __launch_bounds__(256) void k_gemm2_fused(const float* __restrict__ B,
                                                     const float* __restrict__ b1) {
    __shared__ __align__(16) uint32_t As[128][36];
    __shared__ __align__(16) uint32_t Bs[32][72];    // pad72: b-frag conflict-free

    const int tid = threadIdx.x;
    const int lane = tid & 31;
    const int warp = tid >> 5;        // 0..7
    const int wm = warp & 3;
    const int wn = warp >> 2;
    const int gp = lane >> 2;
    const int tq = lane & 3;

    const int rowBase = blockIdx.x * 128;
    const int warpRow = wm * 32;
    const int warpCol = wn * 32;

    float acc[2][4][4];
#pragma unroll
    for (int mi = 0; mi < 2; mi++)
#pragma unroll
        for (int ni = 0; ni < 4; ni++)
#pragma unroll
            for (int j = 0; j < 4; j++) acc[mi][ni][j] = 0.f;

    for (int k0 = 0; k0 < NH; k0 += 32) {
        // ---- A tile: gather+aggregate from g_h1, 1024 float4 -> 4 per thread.
        // 8 consecutive threads cover one row's 32-k chunk (coalesced 128B per neighbor).
#pragma unroll
        for (int i = 0; i < 4; i++) {
            int fid = tid + i * 256;
            int r = fid >> 3, q = fid & 7;
            int gr = rowBase + r;
            float4 a4 = make_float4(0.f, 0.f, 0.f, 0.f);
            if (gr < NN) {
                int s = __ldg(&g_offs[gr]), e = __ldg(&g_offs[gr + 1]);
                for (int p = s; p < e; p++) {
                    int nb = __ldg(&g_adj[p]);
                    float4 v = __ldg((const float4*)(g_h1 + (size_t)nb * NH + k0 + q * 4));
                    a4.x += v.x; a4.y += v.y; a4.z += v.z; a4.w += v.w;
                }
                float d = g_dinv[gr];
                float4 bb = __ldg((const float4*)(b1 + k0 + q * 4));
                a4.x = fmaxf(d * a4.x + bb.x, 0.f);
                a4.y = fmaxf(d * a4.y + bb.y, 0.f);
                a4.z = fmaxf(d * a4.z + bb.z, 0.f);
                a4.w = fmaxf(d * a4.w + bb.w, 0.f);
            }
            uint4 u;
            u.x = f2tf32(a4.x); u.y = f2tf32(a4.y);
            u.z = f2tf32(a4.z); u.w = f2tf32(a4.w);
            *(uint4*)(&As[r][q * 4]) = u;
        }
        // ---- B tile: 32 x 64 scalar with col guard (W2 row stride = 47)
#pragma unroll
        for (int i = 0; i < 8; i++) {
            int fid = tid + i * 256;
            int r = fid >> 6, c = fid & 63;
            float v = (c < NC) ? __ldg(B + (size_t)(k0 + r) * NC + c) : 0.f;
            Bs[r][c] = f2tf32(v);
        }
        __syncthreads();

#pragma unroll
        for (int kk = 0; kk < 32; kk += 8) {
            uint32_t a[2][4];
#pragma unroll
            for (int mi = 0; mi < 2; mi++) {
                int r0 = warpRow + mi * 16 + gp;
                a[mi][0] = As[r0][kk + tq];
                a[mi][1] = As[r0 + 8][kk + tq];
                a[mi][2] = As[r0][kk + tq + 4];
                a[mi][3] = As[r0 + 8][kk + tq + 4];
            }
            uint32_t b[4][2];
#pragma unroll
            for (int ni = 0; ni < 4; ni++) {
                int c = warpCol + ni * 8 + gp;
                b[ni][0] = Bs[kk + tq][c];
                b[ni][1] = Bs[kk + tq + 4][c];
            }
#pragma unroll
            for (int mi = 0; mi < 2; mi++)
#pragma unroll
                for (int ni = 0; ni < 4; ni++)
                    mma_tf32(acc[mi][ni][0], acc[mi][ni][1],
                             acc[mi][ni][2], acc[mi][ni][3],
                             a[mi][0], a[mi][1], a[mi][2], a[mi][3],
                             b[ni][0], b[ni][1]);
        }
        __syncthreads();
    }

    // ---- epilogue with N guard
#pragma unroll
    for (int mi = 0; mi < 2; mi++) {
        int r0 = rowBase + warpRow + mi * 16 + gp;
        int r1 = r0 + 8;
        float d0 = (r0 < NN) ? g_dinv[r0] : 0.f;
        float d1 = (r1 < NN) ? g_dinv[r1] : 0.f;
#pragma unroll
        for (int ni = 0; ni < 4; ni++) {
            int c = warpCol + ni * 8 + tq * 2;
            if (r0 < NN) {
                if (c < NC)     g_h2[(size_t)r0 * NC + c]     = d0 * acc[mi][ni][0];
                if (c + 1 < NC) g_h2[(size_t)r0 * NC + c + 1] = d0 * acc[mi][ni][1];
            }
            if (r1 < NN) {
                if (c < NC)     g_h2[(size_t)r1 * NC + c]     = d1 * acc[mi][ni][2];
                if (c + 1 < NC) g_h2[(size_t)r1 * NC + c + 1] = d1 * acc[mi][ni][3];
            }
        }
    }
}

// ---------------- agg2: out[i,c] = dinv[i]*sum_{adj} h2[row,c] + b2[c] ----------------
__global__ __launch_bounds__(256) void k_agg2(const float* __restrict__ b2,
                                              float* __restrict__ out) {
    int node = blockIdx.x * 8 + (threadIdx.x >> 5);
    if (node >= NN) return;
    int lane = threadIdx.x & 31;
    int s = g_offs[node], e = g_offs[node + 1];
    float a0 = 0.f, a1 = 0.f;
    for (int p = s; p < e; p++) {
        int r = g_adj[p];
        const float* gp = g_h2 + (size_t)r * NC;
        a0 += gp[lane];
        if (lane + 32 < NC) a1 += gp[lane + 32];
    }
    float d = g_dinv[node];
    out[(size_t)node * NC + lane] = d * a0 + b2[lane];
    if (lane + 32 < NC)
        out[(size_t)node * NC + lane + 32] = d * a1 + b2[lane + 32];
}

// ---------------- launch ----------------
extern "C" void kernel_launch(void* const* d_in, const int* in_sizes, int n_in,
                              void* d_out, int out_size) {
    const float* x  = (const float*)d_in[0];
    const int*   ei = (const int*)d_in[1];   // [2, NE] int32
    const float* W1 = (const float*)d_in[2];
    const float* b1 = (const float*)d_in[3];
    const float* W2 = (const float*)d_in[4];
    const float* b2 = (const float*)d_in[5];
    float* out = (float*)d_out;

    const int* erow = ei;        // edge_index[0] = source
    const int* ecol = ei + NE;   // edge_index[1] = target

    // graph prep
    k_init_deg<<<(NN + 255) / 256, 256>>>();
    k_count_deg<<<(NE + 255) / 256, 256>>>(ecol);
    int nsb = (NN + 511) / 512;  // 98
    k_scan_block<<<nsb, 512>>>();
    k_scan_bsum<<<1, 128>>>(nsb);
    k_scan_finish<<<(NN + 255) / 256, 256>>>();
    k_scatter<<<(NADJ + 255) / 256, 256>>>(erow, ecol);

    // layer 1 GEMM
    dim3 g1(NH / 128, (NN + 127) / 128);
    k_gemm1_tf32<<<g1, 128>>>(x, W1);

    // fused agg1 + layer 2 GEMM
    k_gemm2_fused<<<(NN + 127) / 128, 256>>>(W2, b1);

    // final aggregation
    k_agg2<<<(NN + 7) / 8, 256>>>(b2, out);
}

// round 6
// speedup vs baseline: 1.5469x; 1.5469x over previous
#include <cuda_runtime.h>
#include <cuda_bf16.h>
#include <cstdint>

// Problem constants
#define NN 50000
#define NE 150000
#define DF 512
#define NH 512
#define NC 47
#define NADJ (NE + NN)

// ---------------- scratch (static __device__ — no allocation) ----------------
__device__ int   g_deg[NN];
__device__ __align__(16) float g_dinv[NN];
__device__ int   g_incl[NN];
__device__ int   g_bsum[128];
__device__ int   g_offs[NN + 1];
__device__ int   g_cursor[NN];
__device__ int   g_adj[NADJ];
__device__ __align__(16) float g_h1[(size_t)NN * NH];   // dinv-scaled x@W1
__device__ __align__(16) float g_a1[(size_t)NN * NH];   // relu(agg1 + b1)
__device__ __align__(16) float g_h2[(size_t)NN * NC];   // dinv-scaled layer2 pre-agg

// ---------------- graph prep ----------------
__global__ void k_init_deg() {
    int i = blockIdx.x * blockDim.x + threadIdx.x;
    if (i < NN) g_deg[i] = 1;  // self loop
}

__global__ void k_count_deg(const int* __restrict__ ecol) {
    int e = blockIdx.x * blockDim.x + threadIdx.x;
    if (e < NE) atomicAdd(&g_deg[ecol[e]], 1);
}

__global__ void k_scan_block() {
    __shared__ int s[512];
    int i = blockIdx.x * 512 + threadIdx.x;
    int v = (i < NN) ? g_deg[i] : 0;
    s[threadIdx.x] = v;
    __syncthreads();
    for (int off = 1; off < 512; off <<= 1) {
        int t = (threadIdx.x >= off) ? s[threadIdx.x - off] : 0;
        __syncthreads();
        s[threadIdx.x] += t;
        __syncthreads();
    }
    if (i < NN) g_incl[i] = s[threadIdx.x];
    if (threadIdx.x == 511) g_bsum[blockIdx.x] = s[511];
}

// parallel exclusive scan of the 98 block sums (one 128-thread block)
__global__ void k_scan_bsum(int nblocks) {
    __shared__ int s[128];
    int t = threadIdx.x;
    int v = (t < nblocks) ? g_bsum[t] : 0;
    s[t] = v;
    __syncthreads();
    for (int off = 1; off < 128; off <<= 1) {
        int u = (t >= off) ? s[t - off] : 0;
        __syncthreads();
        s[t] += u;
        __syncthreads();
    }
    if (t < nblocks) g_bsum[t] = s[t] - v;  // exclusive
}

__global__ void k_scan_finish() {
    int i = blockIdx.x * blockDim.x + threadIdx.x;
    if (i < NN) {
        int e = g_incl[i] - g_deg[i] + g_bsum[i / 512];
        g_offs[i] = e;
        g_cursor[i] = e;
        g_dinv[i] = rsqrtf((float)g_deg[i]);
    }
    if (i == 0) g_offs[NN] = NADJ;
}

__global__ void k_scatter(const int* __restrict__ erow,
                          const int* __restrict__ ecol) {
    int t = blockIdx.x * blockDim.x + threadIdx.x;
    if (t < NE) {
        int c = ecol[t];
        int p = atomicAdd(&g_cursor[c], 1);
        g_adj[p] = erow[t];
    } else if (t < NADJ) {
        int i = t - NE;
        int p = atomicAdd(&g_cursor[i], 1);
        g_adj[p] = i;
    }
}

// ---------------- helpers ----------------
__device__ __forceinline__ uint32_t f2tf32(float f) {
    uint32_t u;
    asm("cvt.rna.tf32.f32 %0, %1;" : "=r"(u) : "f"(f));
    return u;
}

__device__ __forceinline__ void mma_tf32(float& c0, float& c1, float& c2, float& c3,
                                         uint32_t a0, uint32_t a1, uint32_t a2, uint32_t a3,
                                         uint32_t b0, uint32_t b1) {
    asm volatile(
        "mma.sync.aligned.m16n8k8.row.col.f32.tf32.tf32.f32 "
        "{%0,%1,%2,%3},{%4,%5,%6,%7},{%8,%9},{%0,%1,%2,%3};"
        : "+f"(c0), "+f"(c1), "+f"(c2), "+f"(c3)
        : "r"(a0), "r"(a1), "r"(a2), "r"(a3), "r"(b0), "r"(b1));
}

__device__ __forceinline__ void cp16(uint32_t dst_smem, const void* src, bool pred) {
    int sz = pred ? 16 : 0;
    asm volatile("cp.async.cg.shared.global [%0], [%1], 16, %2;\n"
                 :: "r"(dst_smem), "l"(src), "r"(sz));
}

// ---------------- GEMM1 (TF32, 2-stage cp.async pipeline) ----------------
// g_h1[m,f] = dinv[m] * sum_k x[m,k] * W1[k,f]
// BM=128, BN=128, BK=32; 128 threads = 4 warps (2M x 2N); warp tile 64x64.
// Dynamic SMEM: 2 stages x (A raw fp32 [128][36] + B raw fp32 [32][136]).
#define G1_ASTRIDE 36
#define G1_BSTRIDE 136
#define G1_AELEMS (128 * G1_ASTRIDE)                 // 4608 words
#define G1_STAGE  (G1_AELEMS + 32 * G1_BSTRIDE)      // 8960 words
#define G1_SMEM_BYTES (2 * G1_STAGE * 4)             // 71680 B

__global__ __launch_bounds__(128) void k_gemm1_tf32(const float* __restrict__ A,
                                                    const float* __restrict__ B) {
    extern __shared__ __align__(16) uint32_t dynsm[];

    const int tid = threadIdx.x;
    const int lane = tid & 31;
    const int warp = tid >> 5;        // 0..3
    const int wm = warp & 1;
    const int wn = warp >> 1;
    const int gp = lane >> 2;         // 0..7
    const int tq = lane & 3;          // 0..3

    const int rowBase = blockIdx.y * 128;
    const int colBase = blockIdx.x * 128;
    const int warpRow = wm * 64;
    const int warpCol = wn * 64;

    uint32_t smem_u32;
    {
        void* p = (void*)dynsm;
        smem_u32 = (uint32_t)__cvta_generic_to_shared(p);
    }

    // per-thread copy coordinates (8 A float4 + 8 B float4 per stage)
    // A: fid = tid + i*128 -> r = fid>>3 (0..127), q = fid&7
    // B: fid = tid + i*128 -> r = fid>>5 (0..31),  q = fid&31
    float acc[4][8][4];
#pragma unroll
    for (int mi = 0; mi < 4; mi++)
#pragma unroll
        for (int ni = 0; ni < 8; ni++)
#pragma unroll
            for (int j = 0; j < 4; j++) acc[mi][ni][j] = 0.f;

    const int NT = DF / 32;  // 16 tiles

    // ---- stage loader
    auto load_stage = [&](int st, int k0) {
        uint32_t aBase = smem_u32 + (uint32_t)(st * G1_STAGE) * 4u;
        uint32_t bBase = aBase + (uint32_t)G1_AELEMS * 4u;
#pragma unroll
        for (int i = 0; i < 8; i++) {
            int fid = tid + i * 128;
            int r = fid >> 3, q = fid & 7;
            int gr = rowBase + r;
            bool ok = gr < NN;
            const float* src = A + (size_t)(ok ? gr : 0) * DF + k0 + q * 4;
            cp16(aBase + (uint32_t)(r * G1_ASTRIDE + q * 4) * 4u, src, ok);
        }
#pragma unroll
        for (int i = 0; i < 8; i++) {
            int fid = tid + i * 128;
            int r = fid >> 5, q = fid & 31;
            const float* src = B + (size_t)(k0 + r) * NH + colBase + q * 4;
            cp16(bBase + (uint32_t)(r * G1_BSTRIDE + q * 4) * 4u, src, true);
        }
    };

    load_stage(0, 0);
    asm volatile("cp.async.commit_group;\n");

    for (int t = 0; t < NT; t++) {
        if (t + 1 < NT) load_stage((t + 1) & 1, (t + 1) * 32);
        asm volatile("cp.async.commit_group;\n");
        if (t + 1 < NT) asm volatile("cp.async.wait_group 1;\n");
        else            asm volatile("cp.async.wait_group 0;\n");
        __syncthreads();

        const uint32_t* AsS = dynsm + (t & 1) * G1_STAGE;
        const uint32_t* BsS = AsS + G1_AELEMS;

#pragma unroll
        for (int kk = 0; kk < 32; kk += 8) {
            uint32_t a[4][4];
#pragma unroll
            for (int mi = 0; mi < 4; mi++) {
                int r0 = warpRow + mi * 16 + gp;
                a[mi][0] = f2tf32(__uint_as_float(AsS[r0 * G1_ASTRIDE + kk + tq]));
                a[mi][1] = f2tf32(__uint_as_float(AsS[(r0 + 8) * G1_ASTRIDE + kk + tq]));
                a[mi][2] = f2tf32(__uint_as_float(AsS[r0 * G1_ASTRIDE + kk + tq + 4]));
                a[mi][3] = f2tf32(__uint_as_float(AsS[(r0 + 8) * G1_ASTRIDE + kk + tq + 4]));
            }
            uint32_t b[8][2];
#pragma unroll
            for (int ni = 0; ni < 8; ni++) {
                int c = warpCol + ni * 8 + gp;
                b[ni][0] = f2tf32(__uint_as_float(BsS[(kk + tq) * G1_BSTRIDE + c]));
                b[ni][1] = f2tf32(__uint_as_float(BsS[(kk + tq + 4) * G1_BSTRIDE + c]));
            }
#pragma unroll
            for (int mi = 0; mi < 4; mi++)
#pragma unroll
                for (int ni = 0; ni < 8; ni++)
                    mma_tf32(acc[mi][ni][0], acc[mi][ni][1],
                             acc[mi][ni][2], acc[mi][ni][3],
                             a[mi][0], a[mi][1], a[mi][2], a[mi][3],
                             b[ni][0], b[ni][1]);
        }
        __syncthreads();
    }

    // ---- epilogue: scale rows by dinv, store
#pragma unroll
    for (int mi = 0; mi < 4; mi++) {
        int r0 = rowBase + warpRow + mi * 16 + gp;
        int r1 = r0 + 8;
        float d0 = (r0 < NN) ? g_dinv[r0] : 0.f;
        float d1 = (r1 < NN) ? g_dinv[r1] : 0.f;
#pragma unroll
        for (int ni = 0; ni < 8; ni++) {
            int c = colBase + warpCol + ni * 8 + tq * 2;
            if (r0 < NN) {
                float2 o = make_float2(d0 * acc[mi][ni][0], d0 * acc[mi][ni][1]);
                *(float2*)(g_h1 + (size_t)r0 * NH + c) = o;
            }
            if (r1 < NN) {
                float2 o = make_float2(d1 * acc[mi][ni][2], d1 * acc[mi][ni][3]);
                *(float2*)(g_h1 + (size_t)r1 * NH + c) = o;
            }
        }
    }
}

// ---------------- agg1: a1[i,f] = relu(dinv[i]*sum_{adj} h1[row,f] + b1[f]) ----------------
__global__ __launch_bounds__(128) void k_agg1(const float* __restrict__ b1) {
    const int node = blockIdx.x;
    const int f = threadIdx.x * 4;  // 128 threads x float4 = 512
    const int s = g_offs[node], e = g_offs[node + 1];
    float4 acc = make_float4(0.f, 0.f, 0.f, 0.f);
    for (int p = s; p < e; p++) {
        int r = g_adj[p];
        float4 v = *(const float4*)(g_h1 + (size_t)r * NH + f);
        acc.x += v.x; acc.y += v.y; acc.z += v.z; acc.w += v.w;
    }
    float d = g_dinv[node];
    float4 bb = *(const float4*)(b1 + f);
    float4 o;
    o.x = fmaxf(d * acc.x + bb.x, 0.f);
    o.y = fmaxf(d * acc.y + bb.y, 0.f);
    o.z = fmaxf(d * acc.z + bb.z, 0.f);
    o.w = fmaxf(d * acc.w + bb.w, 0.f);
    *(float4*)(g_a1 + (size_t)node * NH + f) = o;
}

// ---------------- GEMM2 (TF32): g_h2[m,c] = dinv[m] * sum_k a1[m,k] * W2[k,c] ----------------
// BM=128, BN=64 (guarded to 47), BK=32; 256 threads = 8 warps (4M x 2N); warp tile 32x32.
__global__ __launch_bounds__(256) void k_gemm2_tf32(const float* __restrict__ B) {
    __shared__ __align__(16) uint32_t As[128][36];
    __shared__ __align__(16) uint32_t Bs[32][72];    // pad72: b-frag conflict-free

    const int tid = threadIdx.x;
    const int lane = tid & 31;
    const int warp = tid >> 5;        // 0..7
    const int wm = warp & 3;
    const int wn = warp >> 2;
    const int gp = lane >> 2;
    const int tq = lane & 3;

    const int rowBase = blockIdx.x * 128;
    const int warpRow = wm * 32;
    const int warpCol = wn * 32;

    float acc[2][4][4];
#pragma unroll
    for (int mi = 0; mi < 2; mi++)
#pragma unroll
        for (int ni = 0; ni < 4; ni++)
#pragma unroll
            for (int j = 0; j < 4; j++) acc[mi][ni][j] = 0.f;

    for (int k0 = 0; k0 < NH; k0 += 32) {
        // ---- A tile: 128 x 32 = 1024 float4 -> 4 per thread (from g_a1)
#pragma unroll
        for (int i = 0; i < 4; i++) {
            int fid = tid + i * 256;
            int r = fid >> 3, q = fid & 7;
            int gr = rowBase + r;
            float4 v = make_float4(0.f, 0.f, 0.f, 0.f);
            if (gr < NN) v = __ldg((const float4*)(g_a1 + (size_t)gr * NH + k0 + q * 4));
            uint4 u;
            u.x = f2tf32(v.x); u.y = f2tf32(v.y);
            u.z = f2tf32(v.z); u.w = f2tf32(v.w);
            *(uint4*)(&As[r][q * 4]) = u;
        }
        // ---- B tile: 32 x 64 scalar with col guard (W2 row stride = 47)
#pragma unroll
        for (int i = 0; i < 8; i++) {
            int fid = tid + i * 256;
            int r = fid >> 6, c = fid & 63;
            float v = (c < NC) ? __ldg(B + (size_t)(k0 + r) * NC + c) : 0.f;
            Bs[r][c] = f2tf32(v);
        }
        __syncthreads();

#pragma unroll
        for (int kk = 0; kk < 32; kk += 8) {
            uint32_t a[2][4];
#pragma unroll
            for (int mi = 0; mi < 2; mi++) {
                int r0 = warpRow + mi * 16 + gp;
                a[mi][0] = As[r0][kk + tq];
                a[mi][1] = As[r0 + 8][kk + tq];
                a[mi][2] = As[r0][kk + tq + 4];
                a[mi][3] = As[r0 + 8][kk + tq + 4];
            }
            uint32_t b[4][2];
#pragma unroll
            for (int ni = 0; ni < 4; ni++) {
                int c = warpCol + ni * 8 + gp;
                b[ni][0] = Bs[kk + tq][c];
                b[ni][1] = Bs[kk + tq + 4][c];
            }
#pragma unroll
            for (int mi = 0; mi < 2; mi++)
#pragma unroll
                for (int ni = 0; ni < 4; ni++)
                    mma_tf32(acc[mi][ni][0], acc[mi][ni][1],
                             acc[mi][ni][2], acc[mi][ni][3],
                             a[mi][0], a[mi][1], a[mi][2], a[mi][3],
                             b[ni][0], b[ni][1]);
        }
        __syncthreads();
    }

    // ---- epilogue with N guard
#pragma unroll
    for (int mi = 0; mi < 2; mi++) {
        int r0 = rowBase + warpRow + mi * 16 + gp;
        int r1 = r0 + 8;
        float d0 = (r0 < NN) ? g_dinv[r0] : 0.f;
        float d1 = (r1 < NN) ? g_dinv[r1] : 0.f;
#pragma unroll
        for (int ni = 0; ni < 4; ni++) {
            int c = warpCol + ni * 8 + tq * 2;
            if (r0 < NN) {
                if (c < NC)     g_h2[(size_t)r0 * NC + c]     = d0 * acc[mi][ni][0];
                if (c + 1 < NC) g_h2[(size_t)r0 * NC + c + 1] = d0 * acc[mi][ni][1];
            }
            if (r1 < NN) {
                if (c < NC)     g_h2[(size_t)r1 * NC + c]     = d1 * acc[mi][ni][2];
                if (c + 1 < NC) g_h2[(size_t)r1 * NC + c + 1] = d1 * acc[mi][ni][3];
            }
        }
    }
}

// ---------------- agg2: out[i,c] = dinv[i]*sum_{adj} h2[row,c] + b2[c] ----------------
__global__ __launch_bounds__(256) void k_agg2(const float* __restrict__ b2,
                                              float* __restrict__ out) {
    int node = blockIdx.x * 8 + (threadIdx.x >> 5);
    if (node >= NN) return;
    int lane = threadIdx.x & 31;
    int s = g_offs[node], e = g_offs[node + 1];
    float a0 = 0.f, a1 = 0.f;
    for (int p = s; p < e; p++) {
        int r = g_adj[p];
        const float* gp = g_h2 + (size_t)r * NC;
        a0 += gp[lane];
        if (lane + 32 < NC) a1 += gp[lane + 32];
    }
    float d = g_dinv[node];
    out[(size_t)node * NC + lane] = d * a0 + b2[lane];
    if (lane + 32 < NC)
        out[(size_t)node * NC + lane + 32] = d * a1 + b2[lane + 32];
}

// ---------------- launch ----------------
extern "C" void kernel_launch(void* const* d_in, const int* in_sizes, int n_in,
                              void* d_out, int out_size) {
    const float* x  = (const float*)d_in[0];
    const int*   ei = (const int*)d_in[1];   // [2, NE] int32
    const float* W1 = (const float*)d_in[2];
    const float* b1 = (const float*)d_in[3];
    const float* W2 = (const float*)d_in[4];
    const float* b2 = (const float*)d_in[5];
    float* out = (float*)d_out;

    const int* erow = ei;        // edge_index[0] = source
    const int* ecol = ei + NE;   // edge_index[1] = target

    // graph prep
    k_init_deg<<<(NN + 255) / 256, 256>>>();
    k_count_deg<<<(NE + 255) / 256, 256>>>(ecol);
    int nsb = (NN + 511) / 512;  // 98
    k_scan_block<<<nsb, 512>>>();
    k_scan_bsum<<<1, 128>>>(nsb);
    k_scan_finish<<<(NN + 255) / 256, 256>>>();
    k_scatter<<<(NADJ + 255) / 256, 256>>>(erow, ecol);

    // layer 1 GEMM (pipelined TF32)
    cudaFuncSetAttribute(k_gemm1_tf32,
                         cudaFuncAttributeMaxDynamicSharedMemorySize, G1_SMEM_BYTES);
    dim3 g1(NH / 128, (NN + 127) / 128);
    k_gemm1_tf32<<<g1, 128, G1_SMEM_BYTES>>>(x, W1);

    // aggregation 1
    k_agg1<<<NN, 128>>>(b1);

    // layer 2 GEMM
    k_gemm2_tf32<<<(NN + 127) / 128, 256>>>(W2);

    // final aggregation
    k_agg2<<<(NN + 7) / 8, 256>>>(b2, out);
}